// round 1
// baseline (speedup 1.0000x reference)
#include <cuda_runtime.h>
#include <math.h>

#define NN 50000
#define NE 500000
#define NG 2000
#define HD 128

// ---------------- scratch (device globals; no runtime allocation) ----------------
__device__ float f_x1  [NN * HD];
__device__ float f_p   [NN * HD];      // p = x1 @ W1a.T   (also reused as xp in GAT)
__device__ float f_h   [NN * HD];
__device__ float f_xcur[NN * HD];
__device__ float f_gi  [NN * 3 * HD];
__device__ float f_gh  [NN * 3 * HD];
__device__ float f_as  [NN];
__device__ float f_ad  [NN];
__device__ unsigned int u_amax[NN];
__device__ float f_den [NN];
__device__ float g_agg [NG * HD];
__device__ float g_out [NG * HD];
__device__ float g_hh  [NG * HD];
__device__ float g_tmp [NG * HD];
__device__ float g_gi  [NG * 4 * HD];
__device__ float g_gh  [NG * 4 * HD];

// ---------------- helpers ----------------
__device__ __forceinline__ unsigned int fkey(float f) {
    unsigned int i = __float_as_uint(f);
    return (i & 0x80000000u) ? ~i : (i | 0x80000000u);
}
__device__ __forceinline__ float funkey(unsigned int u) {
    return __uint_as_float((u & 0x80000000u) ? (u & 0x7FFFFFFFu) : ~u);
}
__device__ __forceinline__ float sigm(float x) { return 1.0f / (1.0f + expf(-x)); }

// ---------------- zero kernels ----------------
__global__ void zero_f_kernel(float* p, int n) {
    int t = blockIdx.x * blockDim.x + threadIdx.x;
    if (t < n) p[t] = 0.0f;
}
__global__ void zero_u_kernel(unsigned int* p, int n) {
    int t = blockIdx.x * blockDim.x + threadIdx.x;
    if (t < n) p[t] = 0u;
}

// ---------------- generic dense: out[n, jbase+j] = act(sum_k A[n,k]*W[(jbase+j)*wstride+k] + b) --------
// blockDim = 128 (one thread per output channel within a 128-wide j-chunk, blockIdx.y picks chunk)
// ACT: 0 none, 1 leaky(0.01), 2 relu, 3 elu
template <int K, int ACT>
__global__ void __launch_bounds__(128) dense_kernel(
    const float* __restrict__ A, const float* __restrict__ W,
    const float* __restrict__ bias, float* __restrict__ out,
    int n, int Jtotal, int wstride)
{
    constexpr int KP = K + 4;
    constexpr int NT = 8;
    extern __shared__ float sm[];
    float* Ws  = sm;              // 128 * KP
    float* ins = sm + 128 * KP;   // NT * K
    const int tid = threadIdx.x;
    const int jbase = blockIdx.y * 128;

    for (int idx = tid; idx < 128 * K; idx += 128) {
        int r = idx / K, c = idx % K;
        Ws[r * KP + c] = W[(size_t)(jbase + r) * wstride + c];
    }
    float b = bias ? bias[jbase + tid] : 0.0f;
    __syncthreads();

    for (int t0 = blockIdx.x * NT; t0 < n; t0 += gridDim.x * NT) {
        int cnt = min(NT, n - t0);
        for (int idx = tid; idx < cnt * K; idx += 128)
            ins[idx] = A[(size_t)t0 * K + idx];
        __syncthreads();

        float acc[NT];
#pragma unroll
        for (int q = 0; q < NT; ++q) acc[q] = b;

        const float4* wrow = (const float4*)&Ws[tid * KP];
#pragma unroll 4
        for (int k4 = 0; k4 < K / 4; ++k4) {
            float4 w = wrow[k4];
#pragma unroll
            for (int q = 0; q < NT; ++q) {
                float4 v = ((const float4*)&ins[q * K])[k4];
                acc[q] += w.x * v.x + w.y * v.y + w.z * v.z + w.w * v.w;
            }
        }
        for (int q = 0; q < cnt; ++q) {
            float r = acc[q];
            if (ACT == 1) r = (r >= 0.f) ? r : 0.01f * r;
            else if (ACT == 2) r = fmaxf(r, 0.f);
            else if (ACT == 3) r = (r > 0.f) ? r : expm1f(r);
            out[(size_t)(t0 + q) * Jtotal + jbase + tid] = r;
        }
        __syncthreads();
    }
}

// ---------------- nd_conv edge kernel ----------------
// per edge: t = leaky(p[src] + W1b @ ea_e); m = W2 @ t; h[dst] += m
#define EPI 4
__global__ void __launch_bounds__(128) edge_nd_kernel(
    const float* __restrict__ p, const float* __restrict__ ea,
    const int* __restrict__ src, const int* __restrict__ dst,
    const float* __restrict__ w1 /*[128,144]*/, const float* __restrict__ w2 /*[128,128]*/,
    float* __restrict__ hout)
{
    extern __shared__ float sm[];
    float* W1b = sm;                 // 16*128, transposed: W1b[k*128+j]
    float* W2s = W1b + 16 * 128;     // 128*132 padded rows
    float* ts  = W2s + 128 * 132;    // EPI*128
    float* eas = ts + EPI * 128;     // EPI*16
    float* ms  = eas + EPI * 16;     // EPI*128
    int*   meta = (int*)(ms + EPI * 128); // EPI*2
    const int tid = threadIdx.x;

    for (int k = 0; k < 16; ++k)
        W1b[k * 128 + tid] = w1[tid * 144 + 128 + k];
    for (int idx = tid; idx < 128 * 128; idx += 128) {
        int r = idx >> 7, c = idx & 127;
        W2s[r * 132 + c] = w2[idx];
    }
    __syncthreads();

    const int nIter = (NE + EPI - 1) / EPI;
    for (int it = blockIdx.x; it < nIter; it += gridDim.x) {
        int e0 = it * EPI;
        int ecnt = min(EPI, NE - e0);
        if (tid < ecnt * 2) {
            int q = tid >> 1;
            meta[tid] = (tid & 1) ? dst[e0 + q] : src[e0 + q];
        }
        if (tid < ecnt * 16) eas[tid] = ea[(size_t)e0 * 16 + tid];
        __syncthreads();

#pragma unroll
        for (int q = 0; q < EPI; ++q) {
            if (q < ecnt) {
                int s = meta[q * 2];
                float t = p[(size_t)s * 128 + tid];
#pragma unroll
                for (int k = 0; k < 16; ++k)
                    t += W1b[k * 128 + tid] * eas[q * 16 + k];
                ts[q * 128 + tid] = (t >= 0.f) ? t : 0.01f * t;
            }
        }
        __syncthreads();

#pragma unroll
        for (int q = 0; q < EPI; ++q) {
            if (q < ecnt) {
                const float4* wr = (const float4*)&W2s[tid * 132];
                const float4* tv = (const float4*)&ts[q * 128];
                float m = 0.f;
#pragma unroll 8
                for (int k4 = 0; k4 < 32; ++k4) {
                    float4 w = wr[k4]; float4 v = tv[k4];
                    m += w.x * v.x + w.y * v.y + w.z * v.z + w.w * v.w;
                }
                ms[q * 128 + tid] = m;
            }
        }
        __syncthreads();
        {
            int q = tid >> 5, lane = tid & 31;
            if (q < ecnt) {
                int d = meta[q * 2 + 1];
                float4 v = ((const float4*)&ms[q * 128])[lane];
                float* addr = hout + (size_t)d * 128 + lane * 4;
                atomicAdd(addr + 0, v.x);
                atomicAdd(addr + 1, v.y);
                atomicAdd(addr + 2, v.z);
                atomicAdd(addr + 3, v.w);
            }
        }
        __syncthreads();
    }
}

// ---------------- per-node elementwise ----------------
__global__ void bias_elu_kernel(float* h, const float* __restrict__ b, int total) {
    int t = blockIdx.x * blockDim.x + threadIdx.x;
    if (t < total) {
        float v = h[t] + b[t & 127];
        h[t] = (v > 0.f) ? v : expm1f(v);
    }
}

__global__ void gat_fin_kernel(float* h, const float* __restrict__ den,
                               const float* __restrict__ b, int total) {
    int t = blockIdx.x * blockDim.x + threadIdx.x;
    if (t < total) {
        float dd = den[t >> 7];
        float v = (dd > 0.f) ? h[t] / dd : 0.f;
        v += b[t & 127];
        h[t] = (v > 0.f) ? v : expm1f(v);
    }
}

__global__ void gru_combine_kernel(const float* __restrict__ gi, const float* __restrict__ gh,
                                   const float* __restrict__ hprev, float* __restrict__ out, int total) {
    int t = blockIdx.x * blockDim.x + threadIdx.x;
    if (t >= total) return;
    int node = t >> 7, j = t & 127;
    size_t base = (size_t)node * 384;
    float ir = gi[base + j], iz = gi[base + 128 + j], in_ = gi[base + 256 + j];
    float hr = gh[base + j], hz = gh[base + 128 + j], hn  = gh[base + 256 + j];
    float r = sigm(ir + hr);
    float z = sigm(iz + hz);
    float nn = tanhf(in_ + r * hn);
    float hv = hprev[t];
    float o = (1.f - z) * nn + z * hv;
    out[t] = fmaxf(o, 0.f);
}

// ---------------- GAT attention ----------------
__global__ void attn_dots_kernel(const float* __restrict__ xp, const float* __restrict__ asrc,
                                 const float* __restrict__ adst, float* __restrict__ as_,
                                 float* __restrict__ ad_) {
    int n = (blockIdx.x * blockDim.x + threadIdx.x) >> 5;
    int lane = threadIdx.x & 31;
    if (n >= NN) return;
    float4 v = ((const float4*)xp)[(size_t)n * 32 + lane];
    float4 w1 = ((const float4*)asrc)[lane];
    float4 w2 = ((const float4*)adst)[lane];
    float sa = v.x * w1.x + v.y * w1.y + v.z * w1.z + v.w * w1.w;
    float sd = v.x * w2.x + v.y * w2.y + v.z * w2.z + v.w * w2.w;
#pragma unroll
    for (int o = 16; o; o >>= 1) {
        sa += __shfl_xor_sync(0xFFFFFFFFu, sa, o);
        sd += __shfl_xor_sync(0xFFFFFFFFu, sd, o);
    }
    if (lane == 0) { as_[n] = sa; ad_[n] = sd; }
}

__global__ void edge_amax_kernel(const int* __restrict__ src, const int* __restrict__ dst,
                                 const float* __restrict__ as_, const float* __restrict__ ad_,
                                 unsigned int* __restrict__ amax) {
    int e = blockIdx.x * blockDim.x + threadIdx.x;
    if (e < NE) {
        float a = as_[src[e]] + ad_[dst[e]];
        a = (a >= 0.f) ? a : 0.01f * a;
        atomicMax(&amax[dst[e]], fkey(a));
    }
}

__global__ void __launch_bounds__(256) edge_gat_kernel(
    const int* __restrict__ src, const int* __restrict__ dst,
    const float* __restrict__ as_, const float* __restrict__ ad_,
    const unsigned int* __restrict__ amax, const float* __restrict__ xp,
    float* __restrict__ hout, float* __restrict__ den)
{
    int e = (blockIdx.x * blockDim.x + threadIdx.x) >> 5;
    int lane = threadIdx.x & 31;
    if (e >= NE) return;
    int s = src[e], d = dst[e];
    float a = as_[s] + ad_[d];
    a = (a >= 0.f) ? a : 0.01f * a;
    float ae = expf(a - funkey(amax[d]));
    float4 v = ((const float4*)xp)[(size_t)s * 32 + lane];
    float* addr = hout + (size_t)d * 128 + lane * 4;
    atomicAdd(addr + 0, ae * v.x);
    atomicAdd(addr + 1, ae * v.y);
    atomicAdd(addr + 2, ae * v.z);
    atomicAdd(addr + 3, ae * v.w);
    if (lane == 0) atomicAdd(&den[d], ae);
}

// ---------------- readout ----------------
__global__ void __launch_bounds__(128) graph_agg_kernel(const float* __restrict__ xcur,
                                                        const int* __restrict__ batch,
                                                        float* __restrict__ agg,
                                                        float* __restrict__ outv) {
    int g = blockIdx.x;
    int lo, hi;
    {
        int l = 0, r = NN;
        while (l < r) { int m = (l + r) >> 1; if (batch[m] < g) l = m + 1; else r = m; }
        lo = l;
    }
    {
        int l = lo, r = NN;
        while (l < r) { int m = (l + r) >> 1; if (batch[m] < g + 1) l = m + 1; else r = m; }
        hi = l;
    }
    float s = 0.f;
    for (int n = lo; n < hi; ++n) s += xcur[(size_t)n * 128 + threadIdx.x];
    agg[g * 128 + threadIdx.x] = s;
    outv[g * 128 + threadIdx.x] = fmaxf(s, 0.f);
}

__global__ void add_kernel(const float* __restrict__ a, const float* __restrict__ b,
                           float* __restrict__ c, int n) {
    int t = blockIdx.x * blockDim.x + threadIdx.x;
    if (t < n) c[t] = a[t] + b[t];
}

__global__ void lstm_combine_kernel(const float* __restrict__ gi, const float* __restrict__ gh,
                                    const float* __restrict__ hc, float* __restrict__ out) {
    int t = blockIdx.x * blockDim.x + threadIdx.x;
    if (t >= NG * 128) return;
    int g = t >> 7, j = t & 127;
    size_t base = (size_t)g * 512;
    float gI = gi[base + j]       + gh[base + j];
    float gF = gi[base + 128 + j] + gh[base + 128 + j];
    float gG = gi[base + 256 + j] + gh[base + 256 + j];
    float gO = gi[base + 384 + j] + gh[base + 384 + j];
    float c = hc[t];
    float c2 = sigm(gF) * c + sigm(gI) * tanhf(gG);
    out[t] = sigm(gO) * tanhf(c2);
}

__global__ void final_kernel(const float* __restrict__ outv, const float* __restrict__ w,
                             const float* __restrict__ b, float* __restrict__ res) {
    int g = (blockIdx.x * blockDim.x + threadIdx.x) >> 5;
    int lane = threadIdx.x & 31;
    if (g >= NG) return;
    float4 v = ((const float4*)outv)[(size_t)g * 32 + lane];
    float4 ww = ((const float4*)w)[lane];
    float s = v.x * ww.x + v.y * ww.y + v.z * ww.z + v.w * ww.w;
#pragma unroll
    for (int o = 16; o; o >>= 1) s += __shfl_xor_sync(0xFFFFFFFFu, s, o);
    if (lane == 0) res[g] = s + b[0];
}

// ---------------- host ----------------
static inline int imin(int a, int b) { return a < b ? a : b; }

#define SM_D128 ((128 * 132 + 8 * 128) * 4)
#define SM_D64  ((128 * 68 + 8 * 64) * 4)
#define SM_EDGE ((16 * 128 + 128 * 132 + EPI * 128 + EPI * 16 + EPI * 128) * 4 + EPI * 2 * 4)

extern "C" void kernel_launch(void* const* d_in, const int* in_sizes, int n_in,
                              void* d_out, int out_size) {
    const float* x        = (const float*)d_in[0];
    const int*   ei       = (const int*)  d_in[1];
    const float* ea       = (const float*)d_in[2];
    const int*   batch    = (const int*)  d_in[3];
    const float* lin1_w   = (const float*)d_in[4];
    const float* lin1_b   = (const float*)d_in[5];
    const float* nd_lin1w = (const float*)d_in[6];
    const float* nd_lin2w = (const float*)d_in[7];
    const float* nd_bias  = (const float*)d_in[8];
    const float* gru0_wih = (const float*)d_in[9];
    const float* gru0_whh = (const float*)d_in[10];
    const float* gru0_bih = (const float*)d_in[11];
    const float* gru0_bhh = (const float*)d_in[12];
    const float* gat_w    = (const float*)d_in[13];
    const float* gat_asrc = (const float*)d_in[14];
    const float* gat_adst = (const float*)d_in[15];
    const float* gat_b    = (const float*)d_in[16];
    const float* gru_wih  = (const float*)d_in[17];
    const float* gru_whh  = (const float*)d_in[18];
    const float* gru_bih  = (const float*)d_in[19];
    const float* gru_bhh  = (const float*)d_in[20];
    const float* gin_w    = (const float*)d_in[21];
    const float* gin_b    = (const float*)d_in[22];
    const float* lstm_wih = (const float*)d_in[23];
    const float* lstm_whh = (const float*)d_in[24];
    const float* lstm_bih = (const float*)d_in[25];
    const float* lstm_bhh = (const float*)d_in[26];
    const float* lin2_w   = (const float*)d_in[27];
    const float* lin2_b   = (const float*)d_in[28];
    float* out = (float*)d_out;

    const int* src = ei;
    const int* dst = ei + NE;

    // scratch pointers
    float *px1, *pp, *ph, *pxc, *pgi, *pgh, *pas, *pad, *pden;
    float *pagg, *pgout, *pghh, *pgtmp, *pggi, *pggh;
    unsigned int* pam;
    cudaGetSymbolAddress((void**)&px1, f_x1);
    cudaGetSymbolAddress((void**)&pp, f_p);
    cudaGetSymbolAddress((void**)&ph, f_h);
    cudaGetSymbolAddress((void**)&pxc, f_xcur);
    cudaGetSymbolAddress((void**)&pgi, f_gi);
    cudaGetSymbolAddress((void**)&pgh, f_gh);
    cudaGetSymbolAddress((void**)&pas, f_as);
    cudaGetSymbolAddress((void**)&pad, f_ad);
    cudaGetSymbolAddress((void**)&pden, f_den);
    cudaGetSymbolAddress((void**)&pam, u_amax);
    cudaGetSymbolAddress((void**)&pagg, g_agg);
    cudaGetSymbolAddress((void**)&pgout, g_out);
    cudaGetSymbolAddress((void**)&pghh, g_hh);
    cudaGetSymbolAddress((void**)&pgtmp, g_tmp);
    cudaGetSymbolAddress((void**)&pggi, g_gi);
    cudaGetSymbolAddress((void**)&pggh, g_gh);

    cudaFuncSetAttribute(dense_kernel<64, 1>, cudaFuncAttributeMaxDynamicSharedMemorySize, SM_D64);
    cudaFuncSetAttribute(dense_kernel<128, 0>, cudaFuncAttributeMaxDynamicSharedMemorySize, SM_D128);
    cudaFuncSetAttribute(dense_kernel<128, 3>, cudaFuncAttributeMaxDynamicSharedMemorySize, SM_D128);
    cudaFuncSetAttribute(edge_nd_kernel, cudaFuncAttributeMaxDynamicSharedMemorySize, SM_EDGE);

    const int nodeTiles = (NN + 7) / 8;
    const int gTiles = (NG + 7) / 8;
    dim3 gridN1(imin(nodeTiles, 896), 1);
    dim3 gridN3(imin(nodeTiles, 896), 3);
    dim3 gridG1(imin(gTiles, 896), 1);
    dim3 gridG4(imin(gTiles, 896), 4);
    const int ZB = 256;

    // 1) x1 = leaky(x @ lin1_w.T + lin1_b)
    dense_kernel<64, 1><<<gridN1, 128, SM_D64>>>(x, lin1_w, lin1_b, px1, NN, 128, 64);

    // 2) p = x1 @ W1a.T  (W1a = first 128 cols of nd_lin1_w rows, row stride 144)
    dense_kernel<128, 0><<<gridN1, 128, SM_D128>>>(px1, nd_lin1w, nullptr, pp, NN, 128, 144);

    // 3) h = 0 ; edge MLP scatter ; h = elu(h + nd_bias)
    zero_f_kernel<<<(NN * 128 + ZB - 1) / ZB, ZB>>>(ph, NN * 128);
    edge_nd_kernel<<<592, 128, SM_EDGE>>>(pp, ea, src, dst, nd_lin1w, nd_lin2w, ph);
    bias_elu_kernel<<<(NN * 128 + ZB - 1) / ZB, ZB>>>(ph, nd_bias, NN * 128);

    // 4) xcur = relu(gru(h, x1))
    dense_kernel<128, 0><<<gridN3, 128, SM_D128>>>(ph, gru0_wih, gru0_bih, pgi, NN, 384, 128);
    dense_kernel<128, 0><<<gridN3, 128, SM_D128>>>(px1, gru0_whh, gru0_bhh, pgh, NN, 384, 128);
    gru_combine_kernel<<<(NN * 128 + ZB - 1) / ZB, ZB>>>(pgi, pgh, px1, pxc, NN * 128);

    // 5) GAT layers
    for (int l = 0; l < 2; ++l) {
        dense_kernel<128, 0><<<gridN1, 128, SM_D128>>>(pxc, gat_w + (size_t)l * 128 * 128, nullptr, pp, NN, 128, 128);
        attn_dots_kernel<<<(NN * 32 + ZB - 1) / ZB, ZB>>>(pp, gat_asrc + l * 128, gat_adst + l * 128, pas, pad);
        zero_u_kernel<<<(NN + ZB - 1) / ZB, ZB>>>(pam, NN);
        zero_f_kernel<<<(NN + ZB - 1) / ZB, ZB>>>(pden, NN);
        zero_f_kernel<<<(NN * 128 + ZB - 1) / ZB, ZB>>>(ph, NN * 128);
        edge_amax_kernel<<<(NE + ZB - 1) / ZB, ZB>>>(src, dst, pas, pad, pam);
        edge_gat_kernel<<<(NE * 32 + ZB - 1) / ZB, ZB>>>(src, dst, pas, pad, pam, pp, ph, pden);
        gat_fin_kernel<<<(NN * 128 + ZB - 1) / ZB, ZB>>>(ph, pden, gat_b + l * 128, NN * 128);
        dense_kernel<128, 0><<<gridN3, 128, SM_D128>>>(ph, gru_wih + (size_t)l * 384 * 128, gru_bih + l * 384, pgi, NN, 384, 128);
        dense_kernel<128, 0><<<gridN3, 128, SM_D128>>>(pxc, gru_whh + (size_t)l * 384 * 128, gru_bhh + l * 384, pgh, NN, 384, 128);
        gru_combine_kernel<<<(NN * 128 + ZB - 1) / ZB, ZB>>>(pgi, pgh, pxc, pxc, NN * 128);
    }

    // 6) readout
    graph_agg_kernel<<<NG, 128>>>(pxc, batch, pagg, pgout);
    for (int t = 0; t < 2; ++t) {
        add_kernel<<<(NG * 128 + ZB - 1) / ZB, ZB>>>(pgout, pagg, pgtmp, NG * 128);
        dense_kernel<128, 3><<<gridG1, 128, SM_D128>>>(pgtmp, gin_w, gin_b, pghh, NG, 128, 128);
        dense_kernel<128, 0><<<gridG4, 128, SM_D128>>>(pgout, lstm_wih, lstm_bih, pggi, NG, 512, 128);
        dense_kernel<128, 0><<<gridG4, 128, SM_D128>>>(pghh, lstm_whh, lstm_bhh, pggh, NG, 512, 128);
        lstm_combine_kernel<<<(NG * 128 + ZB - 1) / ZB, ZB>>>(pggi, pggh, pghh, pgout);
    }

    // 7) out = g_out @ lin2_w.T + lin2_b
    final_kernel<<<(NG * 32 + 127) / 128, 128>>>(pgout, lin2_w, lin2_b, out);
}